// round 14
// baseline (speedup 1.0000x reference)
#include <cuda_runtime.h>
#include <cuda_fp16.h>
#include <cstdint>

#define NPTS 65536
#define DIN 256
#define DOUT 256
#define NHEAD 8
#define DH 32
#define NTRK 256
#define LSEQ 256

// Scratch (device globals -- no allocations allowed)
__device__ __half g_valh[(size_t)NPTS * DIN];
__device__ __half g_wqkvh[3 * DOUT * DIN];
__device__ __half g_wlinh[DOUT * DIN];
__device__ __half g_qkvh[(size_t)NPTS * 3 * DOUT];
__device__ __half g_ctxh[(size_t)NPTS * DOUT];

// ---------------------------------------------------------------------------
__device__ __forceinline__ uint32_t smem_u32(const void* p) {
    uint32_t a;
    asm("{ .reg .u64 t; cvta.to.shared.u64 t, %1; cvt.u32.u64 %0, t; }" : "=r"(a) : "l"(p));
    return a;
}
__device__ __forceinline__ void cp_async16_s(uint32_t smem, const void* gmem) {
    asm volatile("cp.async.cg.shared.global [%0], [%1], 16;\n" :: "r"(smem), "l"(gmem));
}
__device__ __forceinline__ void cp_commit() { asm volatile("cp.async.commit_group;\n"); }
template <int N> __device__ __forceinline__ void cp_wait() {
    asm volatile("cp.async.wait_group %0;\n" :: "n"(N));
}
__device__ __forceinline__ void ldsm4(uint32_t& r0, uint32_t& r1, uint32_t& r2, uint32_t& r3,
                                      uint32_t addr) {
    asm volatile("ldmatrix.sync.aligned.m8n8.x4.shared.b16 {%0,%1,%2,%3}, [%4];"
                 : "=r"(r0), "=r"(r1), "=r"(r2), "=r"(r3) : "r"(addr));
}
__device__ __forceinline__ void ldsm4t(uint32_t& r0, uint32_t& r1, uint32_t& r2, uint32_t& r3,
                                       uint32_t addr) {
    asm volatile("ldmatrix.sync.aligned.m8n8.x4.trans.shared.b16 {%0,%1,%2,%3}, [%4];"
                 : "=r"(r0), "=r"(r1), "=r"(r2), "=r"(r3) : "r"(addr));
}
__device__ __forceinline__ void mma16816(float* c, const uint32_t* a, uint32_t b0, uint32_t b1) {
    asm volatile(
        "mma.sync.aligned.m16n8k16.row.col.f32.f16.f16.f32 "
        "{%0,%1,%2,%3}, {%4,%5,%6,%7}, {%8,%9}, {%0,%1,%2,%3};"
        : "+f"(c[0]), "+f"(c[1]), "+f"(c[2]), "+f"(c[3])
        : "r"(a[0]), "r"(a[1]), "r"(a[2]), "r"(a[3]), "r"(b0), "r"(b1));
}
__device__ __forceinline__ uint32_t h2u(__half2 h) {
    return *reinterpret_cast<uint32_t*>(&h);
}
__device__ __forceinline__ uint32_t ex2_f16x2(uint32_t x) {
    uint32_t r;
    asm("ex2.approx.f16x2 %0, %1;" : "=r"(r) : "r"(x));
    return r;
}

// ---------------------------------------------------------------------------
// fp32 -> fp16 convert (single kernel for all three tensors)
// ---------------------------------------------------------------------------
#define N4_VAL  (NPTS * DIN / 4)
#define N4_WQKV (3 * DOUT * DIN / 4)
#define N4_WLIN (DOUT * DIN / 4)
__global__ void f2h_all_kernel(const float* __restrict__ v, const float* __restrict__ wq,
                               const float* __restrict__ wl, __half* __restrict__ ov,
                               __half* __restrict__ owq, __half* __restrict__ owl) {
    int i = blockIdx.x * blockDim.x + threadIdx.x;
    const float* in;
    __half* out;
    int j = i;
    if (i < N4_VAL) { in = v; out = ov; }
    else if (i < N4_VAL + N4_WQKV) { in = wq; out = owq; j = i - N4_VAL; }
    else if (i < N4_VAL + N4_WQKV + N4_WLIN) { in = wl; out = owl; j = i - N4_VAL - N4_WQKV; }
    else return;
    float4 x = reinterpret_cast<const float4*>(in)[j];
    reinterpret_cast<__half2*>(out)[2 * j]     = __floats2half2_rn(x.x, x.y);
    reinterpret_cast<__half2*>(out)[2 * j + 1] = __floats2half2_rn(x.z, x.w);
}

// ---------------------------------------------------------------------------
// mma.sync GEMM (champion config, frozen): C[M,Nc] = A[M,256] @ W^T + bias.
// BM=128 BN=128 BK=64; 128 threads, 4 warps 2x2, warp tile 64x64;
// 2-stage cp.async, register double-buffered fragments.
// ---------------------------------------------------------------------------
template <bool OUT_HALF>
__global__ __launch_bounds__(128, 2) void gemm_bias_kernel(
    const __half* __restrict__ A, const __half* __restrict__ W,
    const float* __restrict__ bias, void* __restrict__ Cout,
    int M, int Nc, int K)
{
    constexpr int BM = 128, BN = 128, BK = 64, LDT = 72;
    constexpr int STAGE_B = (BM + BN) * LDT * 2;
    extern __shared__ __align__(16) unsigned char smbuf[];
    const uint32_t smbase = smem_u32(smbuf);

    const int tid = threadIdx.x;
    const int lane = tid & 31, warp = tid >> 5;
    const int wr = warp >> 1, wc = warp & 1;
    const int g = lane >> 2, t4 = lane & 3;
    const int rowBase = blockIdx.x * BM;
    const int colBase = blockIdx.y * BN;
    const int NKB = K >> 6;

    auto load_stage = [&](int s, int kb) {
        uint32_t St = smbase + s * STAGE_B;
        const __half* Ag = A + (size_t)rowBase * K + kb * BK;
        const __half* Wg = W + (size_t)colBase * K + kb * BK;
#pragma unroll
        for (int i = 0; i < 16; i++) {
            int idx = tid + i * 128;
            int r = idx >> 3, c = idx & 7;
            const __half* src = (r < BM) ? (Ag + (size_t)r * K + c * 8)
                                         : (Wg + (size_t)(r - BM) * K + c * 8);
            cp_async16_s(St + (r * LDT + c * 8) * 2, src);
        }
        cp_commit();
    };

    const uint32_t aOff = ((wr * 64 + (lane & 15)) * LDT + (lane >> 4) * 8) * 2;
    const uint32_t bOff = (uint32_t)(BM * LDT * 2) +
                          ((wc * 64 + (lane & 15)) * LDT + (lane >> 4) * 8) * 2;

    uint32_t af[2][4][4];
    uint32_t bf[2][4][4];
    float    cc[4][8][4];
#pragma unroll
    for (int i = 0; i < 4; i++)
#pragma unroll
        for (int j = 0; j < 8; j++)
#pragma unroll
            for (int e = 0; e < 4; e++) cc[i][j][e] = 0.0f;

#define LD_FRAGS(sbase, kk, buf)                                               \
    do {                                                                       \
        uint32_t _a = (sbase) + aOff + (kk) * 32;                              \
        ldsm4(af[buf][0][0], af[buf][0][1], af[buf][0][2], af[buf][0][3], _a); \
        ldsm4(af[buf][1][0], af[buf][1][1], af[buf][1][2], af[buf][1][3], _a + 16 * LDT * 2); \
        ldsm4(af[buf][2][0], af[buf][2][1], af[buf][2][2], af[buf][2][3], _a + 32 * LDT * 2); \
        ldsm4(af[buf][3][0], af[buf][3][1], af[buf][3][2], af[buf][3][3], _a + 48 * LDT * 2); \
        uint32_t _b = (sbase) + bOff + (kk) * 32;                              \
        ldsm4(bf[buf][0][0], bf[buf][0][1], bf[buf][0][2], bf[buf][0][3], _b); \
        ldsm4(bf[buf][1][0], bf[buf][1][1], bf[buf][1][2], bf[buf][1][3], _b + 16 * LDT * 2); \
        ldsm4(bf[buf][2][0], bf[buf][2][1], bf[buf][2][2], bf[buf][2][3], _b + 32 * LDT * 2); \
        ldsm4(bf[buf][3][0], bf[buf][3][1], bf[buf][3][2], bf[buf][3][3], _b + 48 * LDT * 2); \
    } while (0)

#define MMA_STEP(buf)                                                          \
    do {                                                                       \
        _Pragma("unroll")                                                      \
        for (int i = 0; i < 4; i++) {                                          \
            _Pragma("unroll")                                                  \
            for (int j = 0; j < 4; j++) {                                      \
                mma16816(cc[i][2 * j],     af[buf][i], bf[buf][j][0], bf[buf][j][2]); \
                mma16816(cc[i][2 * j + 1], af[buf][i], bf[buf][j][1], bf[buf][j][3]); \
            }                                                                  \
        }                                                                      \
    } while (0)

    load_stage(0, 0);
    load_stage(1, 1);
    cp_wait<1>();
    __syncthreads();
    LD_FRAGS(smbase, 0, 0);

    for (int kb = 0; kb < NKB; kb++) {
        const uint32_t sbase = smbase + (kb & 1) * STAGE_B;
#pragma unroll
        for (int kk = 0; kk < 4; kk++) {
            if (kk < 3) LD_FRAGS(sbase, kk + 1, (kk + 1) & 1);
            MMA_STEP(kk & 1);
        }
        if (kb + 1 < NKB) {
            __syncthreads();
            if (kb + 2 < NKB) { load_stage(kb & 1, kb + 2); cp_wait<1>(); }
            else              { cp_wait<0>(); }
            __syncthreads();
            LD_FRAGS(smbase + ((kb + 1) & 1) * STAGE_B, 0, 0);
        }
    }

#pragma unroll
    for (int i = 0; i < 4; i++) {
        const int r0 = rowBase + wr * 64 + i * 16 + g;
#pragma unroll
        for (int j = 0; j < 8; j++) {
            const int col = colBase + wc * 64 + j * 8 + 2 * t4;
            const float b0 = bias[col], b1 = bias[col + 1];
            if (OUT_HALF) {
                __half* d = reinterpret_cast<__half*>(Cout);
                *reinterpret_cast<__half2*>(d + (size_t)r0 * Nc + col) =
                    __floats2half2_rn(cc[i][j][0] + b0, cc[i][j][1] + b1);
                *reinterpret_cast<__half2*>(d + (size_t)(r0 + 8) * Nc + col) =
                    __floats2half2_rn(cc[i][j][2] + b0, cc[i][j][3] + b1);
            } else {
                float* d = reinterpret_cast<float*>(Cout);
                *reinterpret_cast<float2*>(d + (size_t)r0 * Nc + col) =
                    make_float2(cc[i][j][0] + b0, cc[i][j][1] + b1);
                *reinterpret_cast<float2*>(d + (size_t)(r0 + 8) * Nc + col) =
                    make_float2(cc[i][j][2] + b0, cc[i][j][3] + b1);
            }
        }
    }
#undef LD_FRAGS
#undef MMA_STEP
}

// ---------------------------------------------------------------------------
// Attention, streaming flash-style: keys processed in TWO halves of 128.
// Max-free softmax makes streaming exact (no rescaling needed): per half,
// compute S-half (64 regs), exp2 -> pf-half (32 regs), PV-accumulate into
// f32 O + ones-MMA row sums. Register footprint ~160 -> 3 CTAs/SM.
// ---------------------------------------------------------------------------
__global__ __launch_bounds__(128, 3) void attn_kernel(const __half* __restrict__ qkv,
                                                      __half* __restrict__ ctxout)
{
    constexpr int LDK = 40;
    extern __shared__ __align__(16) unsigned char smbuf[];   // 3 * 20480 = 61440
    __half* Ksm = reinterpret_cast<__half*>(smbuf);
    __half* Vsm = Ksm + 256 * LDK;
    __half* Qsm = Vsm + 256 * LDK;
    const uint32_t kb_ = smem_u32(Ksm), vb_ = smem_u32(Vsm), qb_ = smem_u32(Qsm);

    const int tid = threadIdx.x, lane = tid & 31, warp = tid >> 5;
    const int g = lane >> 2, t4 = lane & 3;
    const int t = blockIdx.x >> 3, h = blockIdx.x & 7;
    const float cs = 0.17677669529663687f * 1.4426950408889634f;  // scale * log2(e)
    const uint32_t ONES = 0x3C003C00u;

    {
        const __half* base = qkv + (size_t)t * 256 * 768 + h * 32;
#pragma unroll
        for (int rr = 0; rr < 2; rr++) {
            int m = tid + rr * 128;
            const __half* row = base + (size_t)m * 768;
            uint32_t qd = qb_ + m * LDK * 2;
            uint32_t kd = kb_ + m * LDK * 2;
            uint32_t vd = vb_ + m * LDK * 2;
#pragma unroll
            for (int q = 0; q < 4; q++) {
                cp_async16_s(qd + q * 16, row + q * 8);
                cp_async16_s(kd + q * 16, row + 256 + q * 8);
                cp_async16_s(vd + q * 16, row + 512 + q * 8);
            }
        }
    }
    cp_commit();
    cp_wait<0>();
    __syncthreads();

    const uint32_t lOff = ((lane & 15) * LDK + (lane >> 4) * 8) * 2;

#pragma unroll 1
    for (int s = 0; s < 4; s++) {
        const int r0 = s * 64 + warp * 16;

        uint32_t aq[2][4];
        uint32_t qaddr = qb_ + r0 * LDK * 2 + lOff;
        ldsm4(aq[0][0], aq[0][1], aq[0][2], aq[0][3], qaddr);
        ldsm4(aq[1][0], aq[1][1], aq[1][2], aq[1][3], qaddr + 32);

        float O[4][4];
        float sm[4];
#pragma unroll
        for (int j = 0; j < 4; j++) { O[j][0] = O[j][1] = O[j][2] = O[j][3] = 0.0f; }
        sm[0] = sm[1] = sm[2] = sm[3] = 0.0f;

#pragma unroll
        for (int hv = 0; hv < 2; hv++) {
            const uint32_t kvoff = hv * 128 * LDK * 2;

            // S-half = Q K^T over keys [hv*128, hv*128+128) : 16 n8-tiles
            float S[16][4];
#pragma unroll
            for (int j = 0; j < 16; j++) { S[j][0] = S[j][1] = S[j][2] = S[j][3] = 0.0f; }
#pragma unroll
            for (int j = 0; j < 8; j++) {
                uint32_t b0[4], b1[4];
                uint32_t ka = kb_ + kvoff + j * 16 * LDK * 2 + lOff;
                ldsm4(b0[0], b0[1], b0[2], b0[3], ka);
                ldsm4(b1[0], b1[1], b1[2], b1[3], ka + 32);
                mma16816(S[2 * j],     aq[0], b0[0], b0[2]);
                mma16816(S[2 * j],     aq[1], b1[0], b1[2]);
                mma16816(S[2 * j + 1], aq[0], b0[1], b0[3]);
                mma16816(S[2 * j + 1], aq[1], b1[1], b1[3]);
            }

            // P-half = exp2(S * cs), 2-at-a-time f16 (max-free)
            uint32_t pf[8][4];
#pragma unroll
            for (int b = 0; b < 8; b++) {
                pf[b][0] = ex2_f16x2(h2u(__floats2half2_rn(S[2 * b][0] * cs, S[2 * b][1] * cs)));
                pf[b][1] = ex2_f16x2(h2u(__floats2half2_rn(S[2 * b][2] * cs, S[2 * b][3] * cs)));
                pf[b][2] = ex2_f16x2(h2u(__floats2half2_rn(S[2 * b + 1][0] * cs, S[2 * b + 1][1] * cs)));
                pf[b][3] = ex2_f16x2(h2u(__floats2half2_rn(S[2 * b + 1][2] * cs, S[2 * b + 1][3] * cs)));
            }

            // O += P-half @ V-half ; row sums += P-half @ ones
#pragma unroll
            for (int b = 0; b < 8; b++) {
                uint32_t v0[4], v1[4];
                uint32_t va = vb_ + kvoff + b * 16 * LDK * 2 + lOff;
                ldsm4t(v0[0], v0[1], v0[2], v0[3], va);
                ldsm4t(v1[0], v1[1], v1[2], v1[3], va + 32);
                mma16816(O[0], pf[b], v0[0], v0[1]);
                mma16816(O[1], pf[b], v0[2], v0[3]);
                mma16816(O[2], pf[b], v1[0], v1[1]);
                mma16816(O[3], pf[b], v1[2], v1[3]);
                mma16816(sm, pf[b], ONES, ONES);
            }
        }

        const float inv0 = 1.0f / sm[0];
        const float inv1 = 1.0f / sm[2];
        __half* d0 = ctxout + (size_t)(t * 256 + r0 + g) * DOUT + h * 32 + 2 * t4;
        __half* d1 = ctxout + (size_t)(t * 256 + r0 + 8 + g) * DOUT + h * 32 + 2 * t4;
#pragma unroll
        for (int nt = 0; nt < 4; nt++) {
            *reinterpret_cast<__half2*>(d0 + nt * 8) =
                __floats2half2_rn(O[nt][0] * inv0, O[nt][1] * inv0);
            *reinterpret_cast<__half2*>(d1 + nt * 8) =
                __floats2half2_rn(O[nt][2] * inv1, O[nt][3] * inv1);
        }
    }
}

// ---------------------------------------------------------------------------
extern "C" void kernel_launch(void* const* d_in, const int* in_sizes, int n_in,
                              void* d_out, int out_size)
{
    const float* values = (const float*)d_in[0];
    const float* wqkv   = (const float*)d_in[1];
    const float* bqkv   = (const float*)d_in[2];
    const float* wlin   = (const float*)d_in[3];
    const float* blin   = (const float*)d_in[4];

    void *p_valh, *p_wqkvh, *p_wlinh, *p_qkvh, *p_ctxh;
    cudaGetSymbolAddress(&p_valh, g_valh);
    cudaGetSymbolAddress(&p_wqkvh, g_wqkvh);
    cudaGetSymbolAddress(&p_wlinh, g_wlinh);
    cudaGetSymbolAddress(&p_qkvh, g_qkvh);
    cudaGetSymbolAddress(&p_ctxh, g_ctxh);

    const int GEMM_SMEM = 73728;
    const int ATTN_SMEM = 61440;
    cudaFuncSetAttribute(gemm_bias_kernel<true>,  cudaFuncAttributeMaxDynamicSharedMemorySize, GEMM_SMEM);
    cudaFuncSetAttribute(gemm_bias_kernel<false>, cudaFuncAttributeMaxDynamicSharedMemorySize, GEMM_SMEM);
    cudaFuncSetAttribute(attn_kernel, cudaFuncAttributeMaxDynamicSharedMemorySize, ATTN_SMEM);

    const int N4_TOTAL = N4_VAL + N4_WQKV + N4_WLIN;
    f2h_all_kernel<<<(N4_TOTAL + 255) / 256, 256>>>(
        values, wqkv, wlin, (__half*)p_valh, (__half*)p_wqkvh, (__half*)p_wlinh);

    gemm_bias_kernel<true><<<dim3(NPTS / 128, 768 / 128), 128, GEMM_SMEM>>>(
        (const __half*)p_valh, (const __half*)p_wqkvh, bqkv, p_qkvh, NPTS, 768, 256);

    attn_kernel<<<NTRK * NHEAD, 128, ATTN_SMEM>>>((const __half*)p_qkvh, (__half*)p_ctxh);

    gemm_bias_kernel<false><<<dim3(NPTS / 128, 256 / 128), 128, GEMM_SMEM>>>(
        (const __half*)p_ctxh, (const __half*)p_wlinh, blin, d_out, NPTS, 256, 256);
}

// round 16
// speedup vs baseline: 1.0072x; 1.0072x over previous
#include <cuda_runtime.h>
#include <cuda_fp16.h>
#include <cstdint>

#define NPTS 65536
#define DIN 256
#define DOUT 256
#define NHEAD 8
#define DH 32
#define NTRK 256
#define LSEQ 256

// Scratch (device globals -- no allocations allowed)
__device__ __half g_valh[(size_t)NPTS * DIN];
__device__ __half g_wqkvh[3 * DOUT * DIN];
__device__ __half g_wlinh[DOUT * DIN];
__device__ __half g_qkvh[(size_t)NPTS * 3 * DOUT];
__device__ __half g_ctxh[(size_t)NPTS * DOUT];

// ---------------------------------------------------------------------------
__device__ __forceinline__ uint32_t smem_u32(const void* p) {
    uint32_t a;
    asm("{ .reg .u64 t; cvta.to.shared.u64 t, %1; cvt.u32.u64 %0, t; }" : "=r"(a) : "l"(p));
    return a;
}
__device__ __forceinline__ void cp_async16_s(uint32_t smem, const void* gmem) {
    asm volatile("cp.async.cg.shared.global [%0], [%1], 16;\n" :: "r"(smem), "l"(gmem));
}
__device__ __forceinline__ void cp_commit() { asm volatile("cp.async.commit_group;\n"); }
template <int N> __device__ __forceinline__ void cp_wait() {
    asm volatile("cp.async.wait_group %0;\n" :: "n"(N));
}
__device__ __forceinline__ void ldsm4(uint32_t& r0, uint32_t& r1, uint32_t& r2, uint32_t& r3,
                                      uint32_t addr) {
    asm volatile("ldmatrix.sync.aligned.m8n8.x4.shared.b16 {%0,%1,%2,%3}, [%4];"
                 : "=r"(r0), "=r"(r1), "=r"(r2), "=r"(r3) : "r"(addr));
}
__device__ __forceinline__ void ldsm4t(uint32_t& r0, uint32_t& r1, uint32_t& r2, uint32_t& r3,
                                       uint32_t addr) {
    asm volatile("ldmatrix.sync.aligned.m8n8.x4.trans.shared.b16 {%0,%1,%2,%3}, [%4];"
                 : "=r"(r0), "=r"(r1), "=r"(r2), "=r"(r3) : "r"(addr));
}
__device__ __forceinline__ void mma16816(float* c, const uint32_t* a, uint32_t b0, uint32_t b1) {
    asm volatile(
        "mma.sync.aligned.m16n8k16.row.col.f32.f16.f16.f32 "
        "{%0,%1,%2,%3}, {%4,%5,%6,%7}, {%8,%9}, {%0,%1,%2,%3};"
        : "+f"(c[0]), "+f"(c[1]), "+f"(c[2]), "+f"(c[3])
        : "r"(a[0]), "r"(a[1]), "r"(a[2]), "r"(a[3]), "r"(b0), "r"(b1));
}
__device__ __forceinline__ uint32_t h2u(__half2 h) {
    return *reinterpret_cast<uint32_t*>(&h);
}
__device__ __forceinline__ uint32_t ex2_f16x2(uint32_t x) {
    uint32_t r;
    asm("ex2.approx.f16x2 %0, %1;" : "=r"(r) : "r"(x));
    return r;
}

// ---------------------------------------------------------------------------
// fp32 -> fp16 convert (single kernel for all three tensors)
// ---------------------------------------------------------------------------
#define N4_VAL  (NPTS * DIN / 4)
#define N4_WQKV (3 * DOUT * DIN / 4)
#define N4_WLIN (DOUT * DIN / 4)
__global__ void f2h_all_kernel(const float* __restrict__ v, const float* __restrict__ wq,
                               const float* __restrict__ wl, __half* __restrict__ ov,
                               __half* __restrict__ owq, __half* __restrict__ owl) {
    int i = blockIdx.x * blockDim.x + threadIdx.x;
    const float* in;
    __half* out;
    int j = i;
    if (i < N4_VAL) { in = v; out = ov; }
    else if (i < N4_VAL + N4_WQKV) { in = wq; out = owq; j = i - N4_VAL; }
    else if (i < N4_VAL + N4_WQKV + N4_WLIN) { in = wl; out = owl; j = i - N4_VAL - N4_WQKV; }
    else return;
    float4 x = reinterpret_cast<const float4*>(in)[j];
    reinterpret_cast<__half2*>(out)[2 * j]     = __floats2half2_rn(x.x, x.y);
    reinterpret_cast<__half2*>(out)[2 * j + 1] = __floats2half2_rn(x.z, x.w);
}

// ---------------------------------------------------------------------------
// mma.sync GEMM (champion config): C[M,Nc] = A[M,256] @ W^T + bias.
// BM=128 BN=128 BK=64; 128 threads, 4 warps 2x2, warp tile 64x64;
// 2-stage cp.async, register double-buffered fragments.
// QSCALE: multiply (acc+bias) by cs for cols < 256 (Q part of qkv) so the
// attention softmax scale is pre-folded into Q.
// ---------------------------------------------------------------------------
template <bool OUT_HALF, bool QSCALE>
__global__ __launch_bounds__(128, 2) void gemm_bias_kernel(
    const __half* __restrict__ A, const __half* __restrict__ W,
    const float* __restrict__ bias, void* __restrict__ Cout,
    int M, int Nc, int K)
{
    constexpr int BM = 128, BN = 128, BK = 64, LDT = 72;
    constexpr int STAGE_B = (BM + BN) * LDT * 2;
    extern __shared__ __align__(16) unsigned char smbuf[];
    const uint32_t smbase = smem_u32(smbuf);

    const int tid = threadIdx.x;
    const int lane = tid & 31, warp = tid >> 5;
    const int wr = warp >> 1, wc = warp & 1;
    const int g = lane >> 2, t4 = lane & 3;
    const int rowBase = blockIdx.x * BM;
    const int colBase = blockIdx.y * BN;
    const int NKB = K >> 6;

    auto load_stage = [&](int s, int kb) {
        uint32_t St = smbase + s * STAGE_B;
        const __half* Ag = A + (size_t)rowBase * K + kb * BK;
        const __half* Wg = W + (size_t)colBase * K + kb * BK;
#pragma unroll
        for (int i = 0; i < 16; i++) {
            int idx = tid + i * 128;
            int r = idx >> 3, c = idx & 7;
            const __half* src = (r < BM) ? (Ag + (size_t)r * K + c * 8)
                                         : (Wg + (size_t)(r - BM) * K + c * 8);
            cp_async16_s(St + (r * LDT + c * 8) * 2, src);
        }
        cp_commit();
    };

    const uint32_t aOff = ((wr * 64 + (lane & 15)) * LDT + (lane >> 4) * 8) * 2;
    const uint32_t bOff = (uint32_t)(BM * LDT * 2) +
                          ((wc * 64 + (lane & 15)) * LDT + (lane >> 4) * 8) * 2;

    uint32_t af[2][4][4];
    uint32_t bf[2][4][4];
    float    cc[4][8][4];
#pragma unroll
    for (int i = 0; i < 4; i++)
#pragma unroll
        for (int j = 0; j < 8; j++)
#pragma unroll
            for (int e = 0; e < 4; e++) cc[i][j][e] = 0.0f;

#define LD_FRAGS(sbase, kk, buf)                                               \
    do {                                                                       \
        uint32_t _a = (sbase) + aOff + (kk) * 32;                              \
        ldsm4(af[buf][0][0], af[buf][0][1], af[buf][0][2], af[buf][0][3], _a); \
        ldsm4(af[buf][1][0], af[buf][1][1], af[buf][1][2], af[buf][1][3], _a + 16 * LDT * 2); \
        ldsm4(af[buf][2][0], af[buf][2][1], af[buf][2][2], af[buf][2][3], _a + 32 * LDT * 2); \
        ldsm4(af[buf][3][0], af[buf][3][1], af[buf][3][2], af[buf][3][3], _a + 48 * LDT * 2); \
        uint32_t _b = (sbase) + bOff + (kk) * 32;                              \
        ldsm4(bf[buf][0][0], bf[buf][0][1], bf[buf][0][2], bf[buf][0][3], _b); \
        ldsm4(bf[buf][1][0], bf[buf][1][1], bf[buf][1][2], bf[buf][1][3], _b + 16 * LDT * 2); \
        ldsm4(bf[buf][2][0], bf[buf][2][1], bf[buf][2][2], bf[buf][2][3], _b + 32 * LDT * 2); \
        ldsm4(bf[buf][3][0], bf[buf][3][1], bf[buf][3][2], bf[buf][3][3], _b + 48 * LDT * 2); \
    } while (0)

#define MMA_STEP(buf)                                                          \
    do {                                                                       \
        _Pragma("unroll")                                                      \
        for (int i = 0; i < 4; i++) {                                          \
            _Pragma("unroll")                                                  \
            for (int j = 0; j < 4; j++) {                                      \
                mma16816(cc[i][2 * j],     af[buf][i], bf[buf][j][0], bf[buf][j][2]); \
                mma16816(cc[i][2 * j + 1], af[buf][i], bf[buf][j][1], bf[buf][j][3]); \
            }                                                                  \
        }                                                                      \
    } while (0)

    load_stage(0, 0);
    load_stage(1, 1);
    cp_wait<1>();
    __syncthreads();
    LD_FRAGS(smbase, 0, 0);

    for (int kb = 0; kb < NKB; kb++) {
        const uint32_t sbase = smbase + (kb & 1) * STAGE_B;
#pragma unroll
        for (int kk = 0; kk < 4; kk++) {
            if (kk < 3) LD_FRAGS(sbase, kk + 1, (kk + 1) & 1);
            MMA_STEP(kk & 1);
        }
        if (kb + 1 < NKB) {
            __syncthreads();
            if (kb + 2 < NKB) { load_stage(kb & 1, kb + 2); cp_wait<1>(); }
            else              { cp_wait<0>(); }
            __syncthreads();
            LD_FRAGS(smbase + ((kb + 1) & 1) * STAGE_B, 0, 0);
        }
    }

    const float QS = 0.17677669529663687f * 1.4426950408889634f;  // scale*log2(e)
#pragma unroll
    for (int i = 0; i < 4; i++) {
        const int r0 = rowBase + wr * 64 + i * 16 + g;
#pragma unroll
        for (int j = 0; j < 8; j++) {
            const int col = colBase + wc * 64 + j * 8 + 2 * t4;
            const float b0 = bias[col], b1 = bias[col + 1];
            float v0 = cc[i][j][0] + b0, v1 = cc[i][j][1] + b1;
            float v2 = cc[i][j][2] + b0, v3 = cc[i][j][3] + b1;
            if (QSCALE && col < 256) { v0 *= QS; v1 *= QS; v2 *= QS; v3 *= QS; }
            if (OUT_HALF) {
                __half* d = reinterpret_cast<__half*>(Cout);
                *reinterpret_cast<__half2*>(d + (size_t)r0 * Nc + col) =
                    __floats2half2_rn(v0, v1);
                *reinterpret_cast<__half2*>(d + (size_t)(r0 + 8) * Nc + col) =
                    __floats2half2_rn(v2, v3);
            } else {
                float* d = reinterpret_cast<float*>(Cout);
                *reinterpret_cast<float2*>(d + (size_t)r0 * Nc + col) = make_float2(v0, v1);
                *reinterpret_cast<float2*>(d + (size_t)(r0 + 8) * Nc + col) = make_float2(v2, v3);
            }
        }
    }
#undef LD_FRAGS
#undef MMA_STEP
}

// ---------------------------------------------------------------------------
// Attention (champion structure, f32 S accumulation). Q arrives pre-scaled by
// cs = scale*log2(e), so P = exp2(S) directly: CVT f32x2->f16x2 + ex2.f16x2.
// Unnormalized P; row sums via ones-MMA (f32); normalize in epilogue.
// ---------------------------------------------------------------------------
__global__ __launch_bounds__(128) void attn_kernel(const __half* __restrict__ qkv,
                                                   __half* __restrict__ ctxout)
{
    constexpr int LDK = 40;
    extern __shared__ __align__(16) unsigned char smbuf[];   // 3 * 20480 = 61440
    __half* Ksm = reinterpret_cast<__half*>(smbuf);
    __half* Vsm = Ksm + 256 * LDK;
    __half* Qsm = Vsm + 256 * LDK;
    const uint32_t kb_ = smem_u32(Ksm), vb_ = smem_u32(Vsm), qb_ = smem_u32(Qsm);

    const int tid = threadIdx.x, lane = tid & 31, warp = tid >> 5;
    const int g = lane >> 2, t4 = lane & 3;
    const int t = blockIdx.x >> 3, h = blockIdx.x & 7;
    const uint32_t ONES = 0x3C003C00u;

    {
        const __half* base = qkv + (size_t)t * 256 * 768 + h * 32;
#pragma unroll
        for (int rr = 0; rr < 2; rr++) {
            int m = tid + rr * 128;
            const __half* row = base + (size_t)m * 768;
            uint32_t qd = qb_ + m * LDK * 2;
            uint32_t kd = kb_ + m * LDK * 2;
            uint32_t vd = vb_ + m * LDK * 2;
#pragma unroll
            for (int q = 0; q < 4; q++) {
                cp_async16_s(qd + q * 16, row + q * 8);
                cp_async16_s(kd + q * 16, row + 256 + q * 8);
                cp_async16_s(vd + q * 16, row + 512 + q * 8);
            }
        }
    }
    cp_commit();
    cp_wait<0>();
    __syncthreads();

    const uint32_t lOff = ((lane & 15) * LDK + (lane >> 4) * 8) * 2;

#pragma unroll 1
    for (int s = 0; s < 4; s++) {
        const int r0 = s * 64 + warp * 16;

        uint32_t aq[2][4];
        uint32_t qaddr = qb_ + r0 * LDK * 2 + lOff;
        ldsm4(aq[0][0], aq[0][1], aq[0][2], aq[0][3], qaddr);
        ldsm4(aq[1][0], aq[1][1], aq[1][2], aq[1][3], qaddr + 32);

        float S[32][4];
#pragma unroll
        for (int j = 0; j < 32; j++) { S[j][0] = S[j][1] = S[j][2] = S[j][3] = 0.0f; }
#pragma unroll
        for (int j = 0; j < 16; j++) {
            uint32_t b0[4], b1[4];
            uint32_t ka = kb_ + j * 16 * LDK * 2 + lOff;
            ldsm4(b0[0], b0[1], b0[2], b0[3], ka);
            ldsm4(b1[0], b1[1], b1[2], b1[3], ka + 32);
            mma16816(S[2 * j],     aq[0], b0[0], b0[2]);
            mma16816(S[2 * j],     aq[1], b1[0], b1[2]);
            mma16816(S[2 * j + 1], aq[0], b0[1], b0[3]);
            mma16816(S[2 * j + 1], aq[1], b1[1], b1[3]);
        }

        // P = exp2(S) (Q pre-scaled by cs); 2-at-a-time f16, max-free
        uint32_t pf[16][4];
#pragma unroll
        for (int b = 0; b < 16; b++) {
            pf[b][0] = ex2_f16x2(h2u(__floats2half2_rn(S[2 * b][0], S[2 * b][1])));
            pf[b][1] = ex2_f16x2(h2u(__floats2half2_rn(S[2 * b][2], S[2 * b][3])));
            pf[b][2] = ex2_f16x2(h2u(__floats2half2_rn(S[2 * b + 1][0], S[2 * b + 1][1])));
            pf[b][3] = ex2_f16x2(h2u(__floats2half2_rn(S[2 * b + 1][2], S[2 * b + 1][3])));
        }

        // O = P @ V ; row sums via P @ ones (f32 accumulation)
        float O[4][4];
        float sm[4];
#pragma unroll
        for (int j = 0; j < 4; j++) { O[j][0] = O[j][1] = O[j][2] = O[j][3] = 0.0f; }
        sm[0] = sm[1] = sm[2] = sm[3] = 0.0f;
#pragma unroll
        for (int b = 0; b < 16; b++) {
            uint32_t v0[4], v1[4];
            uint32_t va = vb_ + b * 16 * LDK * 2 + lOff;
            ldsm4t(v0[0], v0[1], v0[2], v0[3], va);
            ldsm4t(v1[0], v1[1], v1[2], v1[3], va + 32);
            mma16816(O[0], pf[b], v0[0], v0[1]);
            mma16816(O[1], pf[b], v0[2], v0[3]);
            mma16816(O[2], pf[b], v1[0], v1[1]);
            mma16816(O[3], pf[b], v1[2], v1[3]);
            mma16816(sm, pf[b], ONES, ONES);
        }

        const float inv0 = 1.0f / sm[0];
        const float inv1 = 1.0f / sm[2];
        __half* d0 = ctxout + (size_t)(t * 256 + r0 + g) * DOUT + h * 32 + 2 * t4;
        __half* d1 = ctxout + (size_t)(t * 256 + r0 + 8 + g) * DOUT + h * 32 + 2 * t4;
#pragma unroll
        for (int nt = 0; nt < 4; nt++) {
            *reinterpret_cast<__half2*>(d0 + nt * 8) =
                __floats2half2_rn(O[nt][0] * inv0, O[nt][1] * inv0);
            *reinterpret_cast<__half2*>(d1 + nt * 8) =
                __floats2half2_rn(O[nt][2] * inv1, O[nt][3] * inv1);
        }
    }
}

// ---------------------------------------------------------------------------
extern "C" void kernel_launch(void* const* d_in, const int* in_sizes, int n_in,
                              void* d_out, int out_size)
{
    const float* values = (const float*)d_in[0];
    const float* wqkv   = (const float*)d_in[1];
    const float* bqkv   = (const float*)d_in[2];
    const float* wlin   = (const float*)d_in[3];
    const float* blin   = (const float*)d_in[4];

    void *p_valh, *p_wqkvh, *p_wlinh, *p_qkvh, *p_ctxh;
    cudaGetSymbolAddress(&p_valh, g_valh);
    cudaGetSymbolAddress(&p_wqkvh, g_wqkvh);
    cudaGetSymbolAddress(&p_wlinh, g_wlinh);
    cudaGetSymbolAddress(&p_qkvh, g_qkvh);
    cudaGetSymbolAddress(&p_ctxh, g_ctxh);

    const int GEMM_SMEM = 73728;
    const int ATTN_SMEM = 61440;
    cudaFuncSetAttribute((gemm_bias_kernel<true, true>),   cudaFuncAttributeMaxDynamicSharedMemorySize, GEMM_SMEM);
    cudaFuncSetAttribute((gemm_bias_kernel<false, false>), cudaFuncAttributeMaxDynamicSharedMemorySize, GEMM_SMEM);
    cudaFuncSetAttribute(attn_kernel, cudaFuncAttributeMaxDynamicSharedMemorySize, ATTN_SMEM);

    const int N4_TOTAL = N4_VAL + N4_WQKV + N4_WLIN;
    f2h_all_kernel<<<(N4_TOTAL + 255) / 256, 256>>>(
        values, wqkv, wlin, (__half*)p_valh, (__half*)p_wqkvh, (__half*)p_wlinh);

    gemm_bias_kernel<true, true><<<dim3(NPTS / 128, 768 / 128), 128, GEMM_SMEM>>>(
        (const __half*)p_valh, (const __half*)p_wqkvh, bqkv, p_qkvh, NPTS, 768, 256);

    attn_kernel<<<NTRK * NHEAD, 128, ATTN_SMEM>>>((const __half*)p_qkvh, (__half*)p_ctxh);

    gemm_bias_kernel<false, false><<<dim3(NPTS / 128, 256 / 128), 128, GEMM_SMEM>>>(
        (const __half*)p_ctxh, (const __half*)p_wlinh, blin, d_out, NPTS, 256, 256);
}